// round 6
// baseline (speedup 1.0000x reference)
#include <cuda_runtime.h>

#define N_NODES 100000
#define HDIM 128
#define NE 1600000
#define NGRAPH 512
#define TDIM 10

// ---------------- scratch (device globals: allocation-free) ----------------
__device__ float g_agg[(size_t)N_NODES * HDIM];
__device__ float g_t[(size_t)N_NODES * HDIM];
__device__ float g_h[(size_t)N_NODES * HDIM];
__device__ float g_colsum[HDIM];
__device__ float g_colsumsq[HDIM];
__device__ float g_scale[HDIM];
__device__ float g_shift[HDIM];
__device__ float g_pooled[NGRAPH * HDIM];
// CSR scratch
__device__ int g_deg[N_NODES];
__device__ int g_off[N_NODES + 1];
__device__ int g_cursor[N_NODES];
__device__ int g_srcs[NE];
__device__ int g_goff[NGRAPH + 1];

// ---------------- packed f32x2 helpers ----------------
#define PACK2F(d, lo, hi)                                            \
    asm("mov.b64 %0, {%1, %2};" : "=l"(d)                            \
        : "r"(__float_as_uint(lo)), "r"(__float_as_uint(hi)))
#define UNPACK2F(lo, hi, s)                                          \
    do {                                                             \
        unsigned _ulo, _uhi;                                         \
        asm("mov.b64 {%0, %1}, %2;" : "=r"(_ulo), "=r"(_uhi) : "l"(s)); \
        lo = __uint_as_float(_ulo); hi = __uint_as_float(_uhi);      \
    } while (0)
#define FFMA2(d, a, b, c)                                            \
    asm("fma.rn.f32x2 %0, %1, %2, %3;" : "=l"(d) : "l"(a), "l"(b), "l"(c))

// ================= CSR build (once per launch) =================
__global__ void hist_kernel(const int* __restrict__ ei) {
    int e = blockIdx.x * blockDim.x + threadIdx.x;
    if (e >= NE) return;
    atomicAdd(&g_deg[ei[NE + e]], 1);
}

__global__ void scan_kernel() {
    __shared__ int warpsums[32];
    const int tid = threadIdx.x;
    const int lane = tid & 31, w = tid >> 5;
    const int CH = (N_NODES + 1023) / 1024;  // 98
    int start = tid * CH;
    int end = start + CH < N_NODES ? start + CH : N_NODES;
    if (start > N_NODES) start = N_NODES;
    int s = 0;
    for (int i = start; i < end; i++) s += g_deg[i];
    int v = s;
#pragma unroll
    for (int d = 1; d < 32; d <<= 1) {
        int t = __shfl_up_sync(~0u, v, d);
        if (lane >= d) v += t;
    }
    if (lane == 31) warpsums[w] = v;
    __syncthreads();
    if (w == 0) {
        int ws = warpsums[lane];
#pragma unroll
        for (int d = 1; d < 32; d <<= 1) {
            int t = __shfl_up_sync(~0u, ws, d);
            if (lane >= d) ws += t;
        }
        warpsums[lane] = ws;
    }
    __syncthreads();
    int base = (w > 0 ? warpsums[w - 1] : 0) + (v - s);
    int run = base;
    for (int i = start; i < end; i++) {
        g_off[i] = run;
        g_cursor[i] = run;
        run += g_deg[i];
    }
    if (tid == 1023) g_off[N_NODES] = run;
}

__global__ void bin_kernel(const int* __restrict__ ei) {
    int e = blockIdx.x * blockDim.x + threadIdx.x;
    if (e >= NE) return;
    int s = ei[e];
    int d = ei[NE + e];
    int pos = atomicAdd(&g_cursor[d], 1);
    g_srcs[pos] = s;
}

// parallel boundary scan over sorted batch -> g_goff (lower_bound table)
__global__ void batch_off_kernel(const int* __restrict__ batch) {
    int i = blockIdx.x * blockDim.x + threadIdx.x;
    if (i >= N_NODES) return;
    int b1 = batch[i];
    int b0 = (i == 0) ? -1 : batch[i - 1];
    for (int g = b0 + 1; g <= b1; g++) g_goff[g] = i;
    if (i == N_NODES - 1)
        for (int g = b1 + 1; g <= NGRAPH; g++) g_goff[g] = N_NODES;
}

// ============ aggregate: agg[n] = x[n] + sum_{e:dst=n} x[src[e]] ============
__global__ void __launch_bounds__(256) aggregate_kernel(
    const float* __restrict__ x, float* __restrict__ agg) {
    unsigned long long tid =
        (unsigned long long)blockIdx.x * blockDim.x + threadIdx.x;
    unsigned node = (unsigned)(tid >> 5);
    if (node >= N_NODES) return;
    unsigned lane = (unsigned)tid & 31u;

    float4 sum = __ldg(reinterpret_cast<const float4*>(x + (size_t)node * HDIM) + lane);
    int e = g_off[node];
    const int e1 = g_off[node + 1];
    for (; e + 1 < e1; e += 2) {
        int s0 = g_srcs[e];
        int s1 = g_srcs[e + 1];
        float4 v0 = __ldg(reinterpret_cast<const float4*>(x + (size_t)s0 * HDIM) + lane);
        float4 v1 = __ldg(reinterpret_cast<const float4*>(x + (size_t)s1 * HDIM) + lane);
        sum.x += v0.x; sum.y += v0.y; sum.z += v0.z; sum.w += v0.w;
        sum.x += v1.x; sum.y += v1.y; sum.z += v1.z; sum.w += v1.w;
    }
    if (e < e1) {
        int s0 = g_srcs[e];
        float4 v0 = __ldg(reinterpret_cast<const float4*>(x + (size_t)s0 * HDIM) + lane);
        sum.x += v0.x; sum.y += v0.y; sum.z += v0.z; sum.w += v0.w;
    }
    reinterpret_cast<float4*>(agg + (size_t)node * HDIM)[lane] = sum;
}

// ============ pooling: contiguous segment sum (batch is sorted) ============
__global__ void pool_csr_kernel(const float* __restrict__ h) {
    int g = blockIdx.x;
    int c = threadIdx.x;
    int r = g_goff[g];
    const int r1 = g_goff[g + 1];
    float s0 = 0.f, s1 = 0.f;
    for (; r + 1 < r1; r += 2) {
        s0 += __ldg(h + (size_t)r * HDIM + c);
        s1 += __ldg(h + (size_t)(r + 1) * HDIM + c);
    }
    if (r < r1) s0 += __ldg(h + (size_t)r * HDIM + c);
    g_pooled[g * HDIM + c] = s0 + s1;
}

// ---------------- fused GEMM (row-pair packed f32x2, W in smem) ----------------
// MODE 0: t = A @ W + b ; accumulate col sum/sumsq (BN)
// MODE 1: h = relu( relu(A*scale+shift) @ W + b )
// Block = 256 = 8 warps; warp handles 8 rows x 128 cols.
// A staged TRANSPOSED per warp: rb_t[k][8 rows]. Row pairs (2p,2p+1) are
// adjacent -> one broadcast LDS.128 yields two packed f32x2 multipliers.
// Lane owns cols [4*lane, 4*lane+4); W splats shared across all 8 rows.
constexpr int WARPS = 8;
constexpr int RPW = 8;
constexpr int RPB = WARPS * RPW;     // 64 rows per block
constexpr int SMEM_FLOATS = HDIM * HDIM + WARPS * RPW * HDIM + WARPS * HDIM;
constexpr size_t SMEM_BYTES = SMEM_FLOATS * sizeof(float);  // 102400

template <int MODE>
__global__ void __launch_bounds__(256, 2) gemm_kernel(
    const float* __restrict__ A,
    const float* __restrict__ W, const float* __restrict__ bias,
    float* __restrict__ outp,
    float* __restrict__ colsum, float* __restrict__ colsumsq) {
    extern __shared__ float smem[];
    float* Wsm = smem;                              // 128*128
    float* rowbuf = smem + HDIM * HDIM;             // 8 warps * [HDIM][8]
    float* redbuf = rowbuf + WARPS * RPW * HDIM;

    const int tid = threadIdx.x;
    const int w = tid >> 5;
    const int lane = tid & 31;

    // ---- cooperative W copy: gmem -> smem ----
    {
        const float4* Wg4 = reinterpret_cast<const float4*>(W);
        float4* Ws4 = reinterpret_cast<float4*>(Wsm);
#pragma unroll
        for (int i = 0; i < (HDIM * HDIM / 4) / 256; i++)
            Ws4[i * 256 + tid] = __ldg(Wg4 + i * 256 + tid);
    }

    const float4 bias4 = __ldg(reinterpret_cast<const float4*>(bias) + lane);

    float* rbw = rowbuf + w * (RPW * HDIM);         // [k][8] floats
    const int rbase = blockIdx.x * RPB + w * RPW;

    // ---- stage 8 rows TRANSPOSED into smem (fused input transform) ----
    // lane -> row_local = lane>>2 (0..7), kgrp = lane&3; 8 float4 loads cover k.
    {
        const int rl = lane >> 2;
        const int kg = lane & 3;
        int row = rbase + rl;
        int rr = row < N_NODES ? row : N_NODES - 1;
        const float4* Arow = reinterpret_cast<const float4*>(A + (size_t)rr * HDIM);
#pragma unroll
        for (int it = 0; it < 8; it++) {
            const int c4 = kg + it * 4;             // float4 index: cols 4*c4..+3
            float4 a = __ldg(Arow + c4);
            if (MODE == 1) {
                float4 sc = __ldg(reinterpret_cast<const float4*>(g_scale) + c4);
                float4 sh = __ldg(reinterpret_cast<const float4*>(g_shift) + c4);
                a.x = fmaxf(fmaf(a.x, sc.x, sh.x), 0.f);
                a.y = fmaxf(fmaf(a.y, sc.y, sh.y), 0.f);
                a.z = fmaxf(fmaf(a.z, sc.z, sh.z), 0.f);
                a.w = fmaxf(fmaf(a.w, sc.w, sh.w), 0.f);
            }
            const int k0 = c4 * 4;
            rbw[(k0 + 0) * 8 + rl] = a.x;
            rbw[(k0 + 1) * 8 + rl] = a.y;
            rbw[(k0 + 2) * 8 + rl] = a.z;
            rbw[(k0 + 3) * 8 + rl] = a.w;
        }
    }
    __syncthreads();  // W copy + staging complete

    // ---- mainloop ----
    // acc[p][j] = { out[2p][4*lane+j], out[2p+1][4*lane+j] }
    unsigned long long acc[4][4];
    {
        unsigned long long b0, b1, b2, b3;
        PACK2F(b0, bias4.x, bias4.x);
        PACK2F(b1, bias4.y, bias4.y);
        PACK2F(b2, bias4.z, bias4.z);
        PACK2F(b3, bias4.w, bias4.w);
#pragma unroll
        for (int p = 0; p < 4; p++) {
            acc[p][0] = b0; acc[p][1] = b1; acc[p][2] = b2; acc[p][3] = b3;
        }
    }

    const float4* Ws4 = reinterpret_cast<const float4*>(Wsm);
#pragma unroll 8
    for (int k = 0; k < HDIM; k++) {
        // two broadcast LDS.128: row pairs {0,1},{2,3} and {4,5},{6,7}
        const ulonglong2 aA = *reinterpret_cast<const ulonglong2*>(rbw + k * 8);
        const ulonglong2 aB = *reinterpret_cast<const ulonglong2*>(rbw + k * 8 + 4);
        const float4 wv = Ws4[k * 32 + lane];
        unsigned long long w0, w1, w2, w3;
        PACK2F(w0, wv.x, wv.x);
        PACK2F(w1, wv.y, wv.y);
        PACK2F(w2, wv.z, wv.z);
        PACK2F(w3, wv.w, wv.w);
        FFMA2(acc[0][0], aA.x, w0, acc[0][0]);
        FFMA2(acc[0][1], aA.x, w1, acc[0][1]);
        FFMA2(acc[0][2], aA.x, w2, acc[0][2]);
        FFMA2(acc[0][3], aA.x, w3, acc[0][3]);
        FFMA2(acc[1][0], aA.y, w0, acc[1][0]);
        FFMA2(acc[1][1], aA.y, w1, acc[1][1]);
        FFMA2(acc[1][2], aA.y, w2, acc[1][2]);
        FFMA2(acc[1][3], aA.y, w3, acc[1][3]);
        FFMA2(acc[2][0], aB.x, w0, acc[2][0]);
        FFMA2(acc[2][1], aB.x, w1, acc[2][1]);
        FFMA2(acc[2][2], aB.x, w2, acc[2][2]);
        FFMA2(acc[2][3], aB.x, w3, acc[2][3]);
        FFMA2(acc[3][0], aB.y, w0, acc[3][0]);
        FFMA2(acc[3][1], aB.y, w1, acc[3][1]);
        FFMA2(acc[3][2], aB.y, w2, acc[3][2]);
        FFMA2(acc[3][3], aB.y, w3, acc[3][3]);
    }

    // ---- epilogue ----
    float s0 = 0.f, s1 = 0.f, s2 = 0.f, s3 = 0.f;
    float q0 = 0.f, q1 = 0.f, q2 = 0.f, q3 = 0.f;
#pragma unroll
    for (int p = 0; p < 4; p++) {
        float4 c0, c1;
        UNPACK2F(c0.x, c1.x, acc[p][0]);
        UNPACK2F(c0.y, c1.y, acc[p][1]);
        UNPACK2F(c0.z, c1.z, acc[p][2]);
        UNPACK2F(c0.w, c1.w, acc[p][3]);
        int row0 = rbase + 2 * p;
        if (MODE == 1) {
            c0.x = fmaxf(c0.x, 0.f); c0.y = fmaxf(c0.y, 0.f);
            c0.z = fmaxf(c0.z, 0.f); c0.w = fmaxf(c0.w, 0.f);
            c1.x = fmaxf(c1.x, 0.f); c1.y = fmaxf(c1.y, 0.f);
            c1.z = fmaxf(c1.z, 0.f); c1.w = fmaxf(c1.w, 0.f);
        }
        if (row0 < N_NODES) {
            reinterpret_cast<float4*>(outp + (size_t)row0 * HDIM)[lane] = c0;
            if (MODE == 0) {
                s0 += c0.x; s1 += c0.y; s2 += c0.z; s3 += c0.w;
                q0 += c0.x * c0.x; q1 += c0.y * c0.y;
                q2 += c0.z * c0.z; q3 += c0.w * c0.w;
            }
        }
        if (row0 + 1 < N_NODES) {
            reinterpret_cast<float4*>(outp + (size_t)(row0 + 1) * HDIM)[lane] = c1;
            if (MODE == 0) {
                s0 += c1.x; s1 += c1.y; s2 += c1.z; s3 += c1.w;
                q0 += c1.x * c1.x; q1 += c1.y * c1.y;
                q2 += c1.z * c1.z; q3 += c1.w * c1.w;
            }
        }
    }

    // ---- BN statistics: block-level reduction, 1 atomic per column ----
    if (MODE == 0) {
        float* rw = redbuf + w * HDIM + 4 * lane;
        rw[0] = s0; rw[1] = s1; rw[2] = s2; rw[3] = s3;
        __syncthreads();
        if (tid < HDIM) {
            float t = 0.f;
#pragma unroll
            for (int ww = 0; ww < WARPS; ww++) t += redbuf[ww * HDIM + tid];
            atomicAdd(&colsum[tid], t);
        }
        __syncthreads();
        rw[0] = q0; rw[1] = q1; rw[2] = q2; rw[3] = q3;
        __syncthreads();
        if (tid < HDIM) {
            float t = 0.f;
#pragma unroll
            for (int ww = 0; ww < WARPS; ww++) t += redbuf[ww * HDIM + tid];
            atomicAdd(&colsumsq[tid], t);
        }
    }
}

// ---------------- BN finalize ----------------
__global__ void bn_finalize(const float* __restrict__ gamma,
                            const float* __restrict__ beta) {
    int i = threadIdx.x;
    const float invn = 1.0f / (float)N_NODES;
    float m = g_colsum[i] * invn;
    float v = g_colsumsq[i] * invn - m * m;
    float istd = rsqrtf(v + 1e-5f);
    float sc = istd * gamma[i];
    g_scale[i] = sc;
    g_shift[i] = beta[i] - m * sc;
}

// ---------------- classifier ----------------
__global__ void final_kernel(const float* __restrict__ Wl,
                             const float* __restrict__ bl,
                             float* __restrict__ out) {
    int g = blockIdx.x * blockDim.x + threadIdx.x;
    if (g >= NGRAPH) return;
    float acc[TDIM];
#pragma unroll
    for (int t = 0; t < TDIM; t++) acc[t] = __ldg(&bl[t]);
    const float* p = g_pooled + (size_t)g * HDIM;
#pragma unroll 8
    for (int k = 0; k < HDIM; k++) {
        float pv = p[k];
#pragma unroll
        for (int t = 0; t < TDIM; t++)
            acc[t] = fmaf(pv, __ldg(&Wl[k * TDIM + t]), acc[t]);
    }
#pragma unroll
    for (int t = 0; t < TDIM; t++) out[g * TDIM + t] = acc[t];
}

// ---------------- launch ----------------
extern "C" void kernel_launch(void* const* d_in, const int* in_sizes, int n_in,
                              void* d_out, int out_size) {
    const float* x = (const float*)d_in[0];
    const int* ei = (const int*)d_in[1];
    const int* batch = (const int*)d_in[2];
    const float* W1a = (const float*)d_in[3];
    const float* b1a = (const float*)d_in[4];
    const float* g1  = (const float*)d_in[5];
    const float* bt1 = (const float*)d_in[6];
    const float* W1b = (const float*)d_in[7];
    const float* b1b = (const float*)d_in[8];
    const float* W2a = (const float*)d_in[9];
    const float* b2a = (const float*)d_in[10];
    const float* g2  = (const float*)d_in[11];
    const float* bt2 = (const float*)d_in[12];
    const float* W2b = (const float*)d_in[13];
    const float* b2b = (const float*)d_in[14];
    const float* Wl  = (const float*)d_in[15];
    const float* bl  = (const float*)d_in[16];
    float* out = (float*)d_out;

    float *aggp, *tp, *hp, *csp, *cqp;
    int* degp;
    cudaGetSymbolAddress((void**)&aggp, g_agg);
    cudaGetSymbolAddress((void**)&tp, g_t);
    cudaGetSymbolAddress((void**)&hp, g_h);
    cudaGetSymbolAddress((void**)&csp, g_colsum);
    cudaGetSymbolAddress((void**)&cqp, g_colsumsq);
    cudaGetSymbolAddress((void**)&degp, g_deg);

    cudaFuncSetAttribute(gemm_kernel<0>,
                         cudaFuncAttributeMaxDynamicSharedMemorySize,
                         (int)SMEM_BYTES);
    cudaFuncSetAttribute(gemm_kernel<1>,
                         cudaFuncAttributeMaxDynamicSharedMemorySize,
                         (int)SMEM_BYTES);

    const int EDGE_BLOCKS = (NE + 255) / 256;
    const int NODE_BLOCKS = (N_NODES + 255) / 256;
    const int AGG_BLOCKS = (int)(((long long)N_NODES * 32 + 255) / 256);
    const int GEMM_BLOCKS = (N_NODES + RPB - 1) / RPB;  // 1563

    // ---- CSR build ----
    cudaMemsetAsync(degp, 0, N_NODES * sizeof(int));
    hist_kernel<<<EDGE_BLOCKS, 256>>>(ei);
    scan_kernel<<<1, 1024>>>();
    bin_kernel<<<EDGE_BLOCKS, 256>>>(ei);
    batch_off_kernel<<<NODE_BLOCKS, 256>>>(batch);

    // ---- GIN layer 1 ----
    aggregate_kernel<<<AGG_BLOCKS, 256>>>(x, aggp);
    cudaMemsetAsync(csp, 0, HDIM * sizeof(float));
    cudaMemsetAsync(cqp, 0, HDIM * sizeof(float));
    gemm_kernel<0><<<GEMM_BLOCKS, 256, SMEM_BYTES>>>(aggp, W1a, b1a, tp, csp, cqp);
    bn_finalize<<<1, HDIM>>>(g1, bt1);
    gemm_kernel<1><<<GEMM_BLOCKS, 256, SMEM_BYTES>>>(tp, W1b, b1b, hp, nullptr, nullptr);

    // ---- GIN layer 2 ----
    aggregate_kernel<<<AGG_BLOCKS, 256>>>(hp, aggp);
    cudaMemsetAsync(csp, 0, HDIM * sizeof(float));
    cudaMemsetAsync(cqp, 0, HDIM * sizeof(float));
    gemm_kernel<0><<<GEMM_BLOCKS, 256, SMEM_BYTES>>>(aggp, W2a, b2a, tp, csp, cqp);
    bn_finalize<<<1, HDIM>>>(g2, bt2);
    gemm_kernel<1><<<GEMM_BLOCKS, 256, SMEM_BYTES>>>(tp, W2b, b2b, hp, nullptr, nullptr);

    // ---- pool + classifier ----
    pool_csr_kernel<<<NGRAPH, HDIM>>>(hp);
    final_kernel<<<(NGRAPH + 255) / 256, 256>>>(Wl, bl, out);
}